// round 4
// baseline (speedup 1.0000x reference)
#include <cuda_runtime.h>
#include <cstdint>

#define D 128
#define MAXN 50176
#define MAXE (1 << 20)
#define TM 64

// ---- scratch (static device globals; no allocation) ----
__device__ float g_y[(size_t)MAXN * D];     // per-layer x@W
__device__ float g_dinv[MAXN];
__device__ int   g_deg[MAXN];
__device__ int   g_src[MAXE];
__device__ int   g_dst[MAXE];
__device__ int   g_is64;

// ---- edge dtype detection: int64 little-endian => odd int32 words all zero ----
__global__ void k_detect(const int* __restrict__ e) {
    __shared__ int any;
    if (threadIdx.x == 0) any = 0;
    __syncthreads();
    for (int i = threadIdx.x; i < 1024; i += blockDim.x) {
        if (e[2 * i + 1] != 0) any = 1;
    }
    __syncthreads();
    if (threadIdx.x == 0) g_is64 = (any == 0) ? 1 : 0;
}

__global__ void k_convert_edges(const void* __restrict__ edges, int E) {
    int i = blockIdx.x * blockDim.x + threadIdx.x;
    if (i >= E) return;
    if (g_is64) {
        const long long* p = (const long long*)edges;
        g_src[i] = (int)p[i];
        g_dst[i] = (int)p[E + i];
    } else {
        const int* p = (const int*)edges;
        g_src[i] = p[i];
        g_dst[i] = p[E + i];
    }
}

// ---- degree / dinv ----
__global__ void k_deg_init(int n) {
    int i = blockIdx.x * blockDim.x + threadIdx.x;
    if (i < n) g_deg[i] = 1;   // self-loop
}

__global__ void k_deg_acc(int E) {
    int i = blockIdx.x * blockDim.x + threadIdx.x;
    if (i < E) atomicAdd(&g_deg[g_dst[i]], 1);
}

__global__ void k_dinv(int n) {
    int i = blockIdx.x * blockDim.x + threadIdx.x;
    if (i < n) g_dinv[i] = rsqrtf((float)g_deg[i]);
}

// ---- copy x0 (vectorized) ----
__global__ void k_copy4(const float4* __restrict__ src, float4* __restrict__ dst, int n4) {
    int i = blockIdx.x * blockDim.x + threadIdx.x;
    if (i < n4) dst[i] = src[i];
}

// ---- GEMM + epilogue: g_y = x @ W ; xnext = b + g_y * dinv^2 (self-loop term) ----
__global__ __launch_bounds__(256) void k_gemm(const float* __restrict__ x,
                                              const float* __restrict__ W,
                                              const float* __restrict__ b,
                                              float* __restrict__ xnext,
                                              int n) {
    __shared__ float Ws[32 * D];    // 16 KB: 32 K-rows x 128 cols
    __shared__ float Xs[TM * 32];   //  8 KB: 64 rows x 32 K-cols
    const int tid = threadIdx.x;
    const int tx  = tid & 31;       // output col group: cols tx*4..tx*4+3
    const int ty  = tid >> 5;       // warp id: rows ty*8..ty*8+7
    const int row0 = blockIdx.x * TM;

    float4 acc[8];
#pragma unroll
    for (int r = 0; r < 8; r++) acc[r] = make_float4(0.f, 0.f, 0.f, 0.f);

    for (int kb = 0; kb < 4; kb++) {
        // load W chunk: rows kb*32..+31, all 128 cols  (1024 float4)
#pragma unroll
        for (int i = 0; i < 4; i++) {
            int lin = tid + i * 256;          // 0..1023
            int wr = lin >> 5, wc = lin & 31; // row, float4-col
            ((float4*)Ws)[lin] = ((const float4*)(W + (size_t)(kb * 32 + wr) * D))[wc];
        }
        // load X chunk: 64 rows x 32 cols (512 float4)
#pragma unroll
        for (int i = 0; i < 2; i++) {
            int lin = tid + i * 256;          // 0..511
            int xr = lin >> 3, xc = lin & 7;
            int gr = row0 + xr;
            float4 v = make_float4(0.f, 0.f, 0.f, 0.f);
            if (gr < n) v = ((const float4*)(x + (size_t)gr * D + kb * 32))[xc];
            ((float4*)Xs)[lin] = v;
        }
        __syncthreads();

#pragma unroll
        for (int kk4 = 0; kk4 < 8; kk4++) {
            float4 w0 = ((float4*)Ws)[(kk4 * 4 + 0) * 32 + tx];
            float4 w1 = ((float4*)Ws)[(kk4 * 4 + 1) * 32 + tx];
            float4 w2 = ((float4*)Ws)[(kk4 * 4 + 2) * 32 + tx];
            float4 w3 = ((float4*)Ws)[(kk4 * 4 + 3) * 32 + tx];
#pragma unroll
            for (int rr = 0; rr < 8; rr++) {
                float4 xv = ((float4*)Xs)[(ty * 8 + rr) * 8 + kk4];
                acc[rr].x = fmaf(xv.x, w0.x, acc[rr].x);
                acc[rr].y = fmaf(xv.x, w0.y, acc[rr].y);
                acc[rr].z = fmaf(xv.x, w0.z, acc[rr].z);
                acc[rr].w = fmaf(xv.x, w0.w, acc[rr].w);
                acc[rr].x = fmaf(xv.y, w1.x, acc[rr].x);
                acc[rr].y = fmaf(xv.y, w1.y, acc[rr].y);
                acc[rr].z = fmaf(xv.y, w1.z, acc[rr].z);
                acc[rr].w = fmaf(xv.y, w1.w, acc[rr].w);
                acc[rr].x = fmaf(xv.z, w2.x, acc[rr].x);
                acc[rr].y = fmaf(xv.z, w2.y, acc[rr].y);
                acc[rr].z = fmaf(xv.z, w2.z, acc[rr].z);
                acc[rr].w = fmaf(xv.z, w2.w, acc[rr].w);
                acc[rr].x = fmaf(xv.w, w3.x, acc[rr].x);
                acc[rr].y = fmaf(xv.w, w3.y, acc[rr].y);
                acc[rr].z = fmaf(xv.w, w3.z, acc[rr].z);
                acc[rr].w = fmaf(xv.w, w3.w, acc[rr].w);
            }
        }
        __syncthreads();
    }

    const float4 bv = ((const float4*)b)[tx];
#pragma unroll
    for (int rr = 0; rr < 8; rr++) {
        int gr = row0 + ty * 8 + rr;
        if (gr < n) {
            float di = g_dinv[gr];
            float nl = di * di;               // self-loop norm
            float4 a = acc[rr];
            ((float4*)(g_y + (size_t)gr * D))[tx] = a;
            float4 o;
            o.x = bv.x + a.x * nl;
            o.y = bv.y + a.y * nl;
            o.z = bv.z + a.z * nl;
            o.w = bv.w + a.w * nl;
            ((float4*)(xnext + (size_t)gr * D))[tx] = o;
        }
    }
}

// ---- edge scatter: out[dst] += y[src] * dinv[src]*dinv[dst]  (one warp / edge) ----
__global__ __launch_bounds__(256) void k_scatter(float* __restrict__ out, int E) {
    int e = blockIdx.x * (blockDim.x >> 5) + (threadIdx.x >> 5);
    if (e >= E) return;
    int lane = threadIdx.x & 31;
    int s  = g_src[e];
    int d2 = g_dst[e];
    float nrm = g_dinv[s] * g_dinv[d2];
    float4 v = ((const float4*)(g_y + (size_t)s * D))[lane];
    float* p = out + (size_t)d2 * D + (size_t)lane * 4;
    asm volatile("red.global.add.v4.f32 [%0], {%1,%2,%3,%4};"
                 :: "l"(p), "f"(v.x * nrm), "f"(v.y * nrm), "f"(v.z * nrm), "f"(v.w * nrm)
                 : "memory");
}

// ---- total = x0+x1+x2+x3 ----
__global__ void k_total(float4* __restrict__ out, int nd4) {
    int i = blockIdx.x * blockDim.x + threadIdx.x;
    if (i >= nd4) return;
    float4 a = out[i + (size_t)nd4];
    float4 b = out[i + (size_t)2 * nd4];
    float4 c = out[i + (size_t)3 * nd4];
    float4 d = out[i + (size_t)4 * nd4];
    float4 t;
    t.x = a.x + b.x + c.x + d.x;
    t.y = a.y + b.y + c.y + d.y;
    t.z = a.z + b.z + c.z + d.z;
    t.w = a.w + b.w + c.w + d.w;
    out[i] = t;
}

extern "C" void kernel_launch(void* const* d_in, const int* in_sizes, int n_in,
                              void* d_out, int out_size) {
    const float* item_emb = (const float*)d_in[0];
    const float* weights  = (const float*)d_in[1];
    const float* biases   = (const float*)d_in[2];
    const void*  edges    = d_in[3];

    const int emb_rows = in_sizes[0] / D;
    const int E        = in_sizes[3] / 2;
    const int n        = out_size / (5 * D);     // 5 concatenated (n,128) outputs
    float* out = (float*)d_out;
    const size_t nd = (size_t)n * D;
    const int nd4 = (int)(nd / 4);

    const float* x0src = item_emb + (size_t)(emb_rows - n) * D;

    // x0 -> out slice 1
    k_copy4<<<(nd4 + 255) / 256, 256>>>((const float4*)x0src, (float4*)(out + nd), nd4);

    // edge dtype detect + convert to int32 scratch
    k_detect<<<1, 256>>>((const int*)edges);
    k_convert_edges<<<(E + 255) / 256, 256>>>(edges, E);

    // degrees (self-loop = init 1) -> dinv
    k_deg_init<<<(n + 255) / 256, 256>>>(n);
    k_deg_acc<<<(E + 255) / 256, 256>>>(E);
    k_dinv<<<(n + 255) / 256, 256>>>(n);

    const int gblocks = (n + TM - 1) / TM;
    for (int l = 0; l < 3; l++) {
        const float* xin = out + nd * (size_t)(1 + l);
        float* xout      = out + nd * (size_t)(2 + l);
        k_gemm<<<gblocks, 256>>>(xin, weights + (size_t)l * D * D,
                                 biases + (size_t)l * D, xout, n);
        const int edges_per_blk = 256 / 32;
        k_scatter<<<(E + edges_per_blk - 1) / edges_per_blk, 256>>>(xout, E);
    }

    k_total<<<(nd4 + 255) / 256, 256>>>((float4*)out, nd4);
}

// round 6
// speedup vs baseline: 1.4936x; 1.4936x over previous
#include <cuda_runtime.h>
#include <cstdint>

#define D 128
#define MAXN 50176
#define MAXE (1 << 20)
#define TM 64

// ---- scratch (static device globals; no allocation) ----
__device__ float g_y[(size_t)MAXN * D];     // per-layer x@W
__device__ float g_dinv[MAXN];
__device__ int   g_deg[MAXN];               // real in-edge count (self-loop excluded)
__device__ int   g_src[MAXE];
__device__ int   g_dst[MAXE];
__device__ int   g_row[MAXN + 1];           // CSR row_start (by dst)
__device__ int   g_rowtmp[MAXN];
__device__ int   g_cur[MAXN];
__device__ int   g_spine[1024];
__device__ int   g_csrc[MAXE];              // CSR: src node per slot
__device__ float g_csw[MAXE];               // CSR: dinv[src] per slot
__device__ int   g_is64;

// ---- packed fp32x2 helpers (sm_103 FFMA2 path) ----
__device__ __forceinline__ unsigned long long pk2(float a, float b) {
    unsigned long long r;
    asm("mov.b64 %0, {%1, %2};" : "=l"(r) : "f"(a), "f"(b));
    return r;
}
__device__ __forceinline__ void fma2(unsigned long long& d, unsigned long long a,
                                     unsigned long long b) {
    asm("fma.rn.f32x2 %0, %1, %2, %0;" : "+l"(d) : "l"(a), "l"(b));
}
__device__ __forceinline__ void unpk2(unsigned long long v, float& a, float& b) {
    asm("mov.b64 {%0, %1}, %2;" : "=f"(a), "=f"(b) : "l"(v));
}

// ---- edge dtype detection: int64 little-endian => odd int32 words all zero ----
__global__ void k_detect(const int* __restrict__ e) {
    __shared__ int any;
    if (threadIdx.x == 0) any = 0;
    __syncthreads();
    for (int i = threadIdx.x; i < 1024; i += blockDim.x) {
        if (e[2 * i + 1] != 0) any = 1;
    }
    __syncthreads();
    if (threadIdx.x == 0) g_is64 = (any == 0) ? 1 : 0;
}

__global__ void k_init(int n) {
    int i = blockIdx.x * blockDim.x + threadIdx.x;
    if (i < n) g_deg[i] = 0;
}

// convert edges to int32 scratch + count in-degrees
__global__ void k_convert(const void* __restrict__ edges, int E) {
    int i = blockIdx.x * blockDim.x + threadIdx.x;
    if (i >= E) return;
    int s, d;
    if (g_is64) {
        const long long* p = (const long long*)edges;
        s = (int)p[i];
        d = (int)p[E + i];
    } else {
        const int* p = (const int*)edges;
        s = p[i];
        d = p[E + i];
    }
    g_src[i] = s;
    g_dst[i] = d;
    atomicAdd(&g_deg[d], 1);
}

// ---- exclusive scan of g_deg -> g_row (3 kernels) ----
__global__ __launch_bounds__(256) void k_scan1(int n) {
    __shared__ int sh[256];
    int i = blockIdx.x * 256 + threadIdx.x;
    int v = (i < n) ? g_deg[i] : 0;
    sh[threadIdx.x] = v;
    __syncthreads();
#pragma unroll
    for (int off = 1; off < 256; off <<= 1) {
        int t = (threadIdx.x >= off) ? sh[threadIdx.x - off] : 0;
        __syncthreads();
        sh[threadIdx.x] += t;
        __syncthreads();
    }
    if (i < n) g_rowtmp[i] = sh[threadIdx.x] - v;   // exclusive
    if (threadIdx.x == 255) g_spine[blockIdx.x] = sh[255];
}

__global__ __launch_bounds__(1024) void k_scan2(int nb) {
    __shared__ int sh[1024];
    int v = (threadIdx.x < nb) ? g_spine[threadIdx.x] : 0;
    sh[threadIdx.x] = v;
    __syncthreads();
#pragma unroll
    for (int off = 1; off < 1024; off <<= 1) {
        int t = (threadIdx.x >= off) ? sh[threadIdx.x - off] : 0;
        __syncthreads();
        sh[threadIdx.x] += t;
        __syncthreads();
    }
    if (threadIdx.x < nb) g_spine[threadIdx.x] = sh[threadIdx.x] - v;  // exclusive
}

__global__ void k_scan3(int n, int E) {
    int i = blockIdx.x * blockDim.x + threadIdx.x;
    if (i >= n) return;
    int rs = g_rowtmp[i] + g_spine[i >> 8];
    g_row[i] = rs;
    g_cur[i] = rs;
    g_dinv[i] = rsqrtf((float)(g_deg[i] + 1));      // +1 self-loop
    if (i == 0) g_row[n] = E;
}

__global__ void k_fill(int E) {
    int e = blockIdx.x * blockDim.x + threadIdx.x;
    if (e >= E) return;
    int s = g_src[e];
    int d = g_dst[e];
    int pos = atomicAdd(&g_cur[d], 1);
    g_csrc[pos] = s;
    g_csw[pos] = g_dinv[s];
}

// ---- copy x0 (vectorized) ----
__global__ void k_copy4(const float4* __restrict__ src, float4* __restrict__ dst, int n4) {
    int i = blockIdx.x * blockDim.x + threadIdx.x;
    if (i < n4) dst[i] = src[i];
}

// ---- GEMM: g_y = x @ W  (fp32 via packed f32x2 FMA) ----
__global__ __launch_bounds__(256) void k_gemm(const float* __restrict__ x,
                                              const float* __restrict__ W,
                                              int n) {
    __shared__ float Ws[32 * D];    // 16 KB: 32 K-rows x 128 cols
    __shared__ float Xs[TM * 32];   //  8 KB: 64 rows x 32 K-cols
    const int tid = threadIdx.x;
    const int tx  = tid & 31;       // output col group: cols tx*4..tx*4+3
    const int ty  = tid >> 5;       // warp id: rows ty*8..ty*8+7
    const int row0 = blockIdx.x * TM;

    unsigned long long acc[8][2];
#pragma unroll
    for (int r = 0; r < 8; r++) { acc[r][0] = 0ull; acc[r][1] = 0ull; }

    for (int kb = 0; kb < 4; kb++) {
        // load W chunk: rows kb*32..+31, all 128 cols  (1024 float4)
#pragma unroll
        for (int i = 0; i < 4; i++) {
            int lin = tid + i * 256;
            int wr = lin >> 5, wc = lin & 31;
            ((float4*)Ws)[lin] = ((const float4*)(W + (size_t)(kb * 32 + wr) * D))[wc];
        }
        // load X chunk: 64 rows x 32 cols (512 float4)
#pragma unroll
        for (int i = 0; i < 2; i++) {
            int lin = tid + i * 256;
            int xr = lin >> 3, xc = lin & 7;
            int gr = row0 + xr;
            float4 v = make_float4(0.f, 0.f, 0.f, 0.f);
            if (gr < n) v = ((const float4*)(x + (size_t)gr * D + kb * 32))[xc];
            ((float4*)Xs)[lin] = v;
        }
        __syncthreads();

#pragma unroll
        for (int kk4 = 0; kk4 < 8; kk4++) {
            float4 w0 = ((float4*)Ws)[(kk4 * 4 + 0) * 32 + tx];
            float4 w1 = ((float4*)Ws)[(kk4 * 4 + 1) * 32 + tx];
            float4 w2 = ((float4*)Ws)[(kk4 * 4 + 2) * 32 + tx];
            float4 w3 = ((float4*)Ws)[(kk4 * 4 + 3) * 32 + tx];
            unsigned long long w0a = pk2(w0.x, w0.y), w0b = pk2(w0.z, w0.w);
            unsigned long long w1a = pk2(w1.x, w1.y), w1b = pk2(w1.z, w1.w);
            unsigned long long w2a = pk2(w2.x, w2.y), w2b = pk2(w2.z, w2.w);
            unsigned long long w3a = pk2(w3.x, w3.y), w3b = pk2(w3.z, w3.w);
#pragma unroll
            for (int rr = 0; rr < 8; rr++) {
                float4 xv = ((float4*)Xs)[(ty * 8 + rr) * 8 + kk4];
                unsigned long long xa = pk2(xv.x, xv.x);
                unsigned long long xb = pk2(xv.y, xv.y);
                unsigned long long xc = pk2(xv.z, xv.z);
                unsigned long long xd = pk2(xv.w, xv.w);
                fma2(acc[rr][0], xa, w0a); fma2(acc[rr][1], xa, w0b);
                fma2(acc[rr][0], xb, w1a); fma2(acc[rr][1], xb, w1b);
                fma2(acc[rr][0], xc, w2a); fma2(acc[rr][1], xc, w2b);
                fma2(acc[rr][0], xd, w3a); fma2(acc[rr][1], xd, w3b);
            }
        }
        __syncthreads();
    }

#pragma unroll
    for (int rr = 0; rr < 8; rr++) {
        int gr = row0 + ty * 8 + rr;
        if (gr < n) {
            float4 a;
            unpk2(acc[rr][0], a.x, a.y);
            unpk2(acc[rr][1], a.z, a.w);
            ((float4*)(g_y + (size_t)gr * D))[tx] = a;
        }
    }
}

// ---- CSR gather: xout[i] = b + dinv[i]^2*y[i] + dinv[i]*sum_e( dinv[src]*y[src] )
//      final flag: also total = x0+x1+x2+x3 ----
__global__ __launch_bounds__(256) void k_gather(const float* __restrict__ bias,
                                                float* __restrict__ xout,
                                                const float* __restrict__ x0,
                                                const float* __restrict__ x1,
                                                const float* __restrict__ x2,
                                                float* __restrict__ total,
                                                int n, int final_layer) {
    int w = (blockIdx.x * blockDim.x + threadIdx.x) >> 5;
    if (w >= n) return;
    int lane = threadIdx.x & 31;
    const float4* yb = (const float4*)g_y;
    const size_t idx = (size_t)w * 32 + lane;

    float di = g_dinv[w];
    float4 ys = yb[idx];
    float4 acc;                         // accumulates di*y_self + sum w_e*y_src, scaled by di at end
    acc.x = ys.x * di; acc.y = ys.y * di; acc.z = ys.z * di; acc.w = ys.w * di;

    int e = g_row[w];
    const int e1 = g_row[w + 1];
    for (; e + 1 < e1; e += 2) {
        int   s0 = g_csrc[e],   s1 = g_csrc[e + 1];
        float u0 = g_csw[e],    u1 = g_csw[e + 1];
        float4 v0 = yb[(size_t)s0 * 32 + lane];
        float4 v1 = yb[(size_t)s1 * 32 + lane];
        acc.x = fmaf(u0, v0.x, acc.x); acc.y = fmaf(u0, v0.y, acc.y);
        acc.z = fmaf(u0, v0.z, acc.z); acc.w = fmaf(u0, v0.w, acc.w);
        acc.x = fmaf(u1, v1.x, acc.x); acc.y = fmaf(u1, v1.y, acc.y);
        acc.z = fmaf(u1, v1.z, acc.z); acc.w = fmaf(u1, v1.w, acc.w);
    }
    if (e < e1) {
        int s0 = g_csrc[e];
        float u0 = g_csw[e];
        float4 v0 = yb[(size_t)s0 * 32 + lane];
        acc.x = fmaf(u0, v0.x, acc.x); acc.y = fmaf(u0, v0.y, acc.y);
        acc.z = fmaf(u0, v0.z, acc.z); acc.w = fmaf(u0, v0.w, acc.w);
    }

    float4 bv = ((const float4*)bias)[lane];
    float4 res;
    res.x = fmaf(acc.x, di, bv.x);
    res.y = fmaf(acc.y, di, bv.y);
    res.z = fmaf(acc.z, di, bv.z);
    res.w = fmaf(acc.w, di, bv.w);
    ((float4*)xout)[idx] = res;

    if (final_layer) {
        float4 a = ((const float4*)x0)[idx];
        float4 b2 = ((const float4*)x1)[idx];
        float4 c = ((const float4*)x2)[idx];
        float4 t;
        t.x = a.x + b2.x + c.x + res.x;
        t.y = a.y + b2.y + c.y + res.y;
        t.z = a.z + b2.z + c.z + res.z;
        t.w = a.w + b2.w + c.w + res.w;
        ((float4*)total)[idx] = t;
    }
}

extern "C" void kernel_launch(void* const* d_in, const int* in_sizes, int n_in,
                              void* d_out, int out_size) {
    const float* item_emb = (const float*)d_in[0];
    const float* weights  = (const float*)d_in[1];
    const float* biases   = (const float*)d_in[2];
    const void*  edges    = d_in[3];

    const int emb_rows = in_sizes[0] / D;
    const int E        = in_sizes[3] / 2;
    const int n        = out_size / (5 * D);     // 5 concatenated (n,128) outputs
    float* out = (float*)d_out;
    const size_t nd = (size_t)n * D;
    const int nd4 = (int)(nd / 4);

    const float* x0src = item_emb + (size_t)(emb_rows - n) * D;

    // x0 -> out slice 1
    k_copy4<<<(nd4 + 255) / 256, 256>>>((const float4*)x0src, (float4*)(out + nd), nd4);

    // edge dtype detect, convert + in-degree count
    k_detect<<<1, 256>>>((const int*)edges);
    k_init<<<(n + 255) / 256, 256>>>(n);
    k_convert<<<(E + 255) / 256, 256>>>(edges, E);

    // CSR build: exclusive scan + fill (also computes dinv)
    const int nb = (n + 255) / 256;
    k_scan1<<<nb, 256>>>(n);
    k_scan2<<<1, 1024>>>(nb);
    k_scan3<<<nb, 256>>>(n, E);
    k_fill<<<(E + 255) / 256, 256>>>(E);

    const int gblocks = (n + TM - 1) / TM;
    const int sblocks = (n + 7) / 8;             // 8 warps (nodes) per 256-thr block
    for (int l = 0; l < 3; l++) {
        const float* xin = out + nd * (size_t)(1 + l);
        float* xout      = out + nd * (size_t)(2 + l);
        k_gemm<<<gblocks, 256>>>(xin, weights + (size_t)l * D * D, n);
        k_gather<<<sblocks, 256>>>(biases + (size_t)l * D, xout,
                                   out + nd, out + 2 * nd, out + 3 * nd, out,
                                   n, (l == 2) ? 1 : 0);
    }
}

// round 10
// speedup vs baseline: 2.0002x; 1.3391x over previous
#include <cuda_runtime.h>
#include <cuda_bf16.h>
#include <cstdint>

#define D 128
#define MAXN 50176
#define MAXE (1 << 20)

// ---- scratch (static device globals; no allocation) ----
__device__ float g_y[(size_t)MAXN * D];     // per-layer x@W (fp32)
__device__ float g_dinv[MAXN];
__device__ int   g_deg[MAXN];
__device__ int   g_row[MAXN + 1];           // CSR row_start (by dst)
__device__ int   g_rowtmp[MAXN];
__device__ int   g_cur[MAXN];
__device__ int   g_spine[1024];
__device__ int   g_csrc[MAXE];              // CSR: src node per slot
__device__ float g_csw[MAXE];               // CSR: dinv[src] per slot
__device__ int   g_is64;
__device__ __nv_bfloat16 g_wh[3 * D * D];   // W^T hi (B layout: [n][k])
__device__ __nv_bfloat16 g_wl[3 * D * D];   // W^T lo

// pack two f32 -> bf16x2 word: lower half = lo_f, upper half = hi_f
#define CVT_BF16X2(res, lo_f, hi_f) \
    asm("cvt.rn.satfinite.bf16x2.f32 %0, %1, %2;" : "=r"(res) : "f"(hi_f), "f"(lo_f))

// D += A * B  (m16n8k16, bf16 in, f32 accum)
#define MMA_BF16(c, a, b0, b1)                                                  \
    asm volatile("mma.sync.aligned.m16n8k16.row.col.f32.bf16.bf16.f32 "         \
        "{%0,%1,%2,%3}, {%4,%5,%6,%7}, {%8,%9}, {%0,%1,%2,%3};"                 \
        : "+f"((c)[0]), "+f"((c)[1]), "+f"((c)[2]), "+f"((c)[3])                \
        : "r"((a)[0]), "r"((a)[1]), "r"((a)[2]), "r"((a)[3]), "r"(b0), "r"(b1))

// ============================================================================
// Setup kernels
// ============================================================================

// copy x0 into out slice 1, and zero degree counters
__global__ void k_copy_init(const float4* __restrict__ src, float4* __restrict__ dst,
                            int n4, int n) {
    int i = blockIdx.x * blockDim.x + threadIdx.x;
    if (i < n4) dst[i] = src[i];
    if (i < n) g_deg[i] = 0;
}

// per-block dtype detect + degree count from raw edges
__global__ void k_count(const int* __restrict__ e32, int E) {
    __shared__ int s_is64;
    if (threadIdx.x == 0) s_is64 = 1;
    __syncthreads();
    if (e32[2 * threadIdx.x + 1] != 0) s_is64 = 0;   // benign race
    __syncthreads();
    int is64 = s_is64;
    int i = blockIdx.x * blockDim.x + threadIdx.x;
    if (i < E) {
        int d = is64 ? (int)((const long long*)e32)[E + i] : e32[E + i];
        atomicAdd(&g_deg[d], 1);
    }
    if (blockIdx.x == 0 && threadIdx.x == 0) g_is64 = is64;
}

// exclusive scan of g_deg -> g_row (3 kernels)
__global__ __launch_bounds__(256) void k_scan1(int n) {
    __shared__ int sh[256];
    int i = blockIdx.x * 256 + threadIdx.x;
    int v = (i < n) ? g_deg[i] : 0;
    sh[threadIdx.x] = v;
    __syncthreads();
#pragma unroll
    for (int off = 1; off < 256; off <<= 1) {
        int t = (threadIdx.x >= off) ? sh[threadIdx.x - off] : 0;
        __syncthreads();
        sh[threadIdx.x] += t;
        __syncthreads();
    }
    if (i < n) g_rowtmp[i] = sh[threadIdx.x] - v;
    if (threadIdx.x == 255) g_spine[blockIdx.x] = sh[255];
}

__global__ __launch_bounds__(1024) void k_scan2(int nb) {
    __shared__ int sh[1024];
    int v = (threadIdx.x < nb) ? g_spine[threadIdx.x] : 0;
    sh[threadIdx.x] = v;
    __syncthreads();
#pragma unroll
    for (int off = 1; off < 1024; off <<= 1) {
        int t = (threadIdx.x >= off) ? sh[threadIdx.x - off] : 0;
        __syncthreads();
        sh[threadIdx.x] += t;
        __syncthreads();
    }
    if (threadIdx.x < nb) g_spine[threadIdx.x] = sh[threadIdx.x] - v;
}

__global__ void k_scan3(int n, int E) {
    int i = blockIdx.x * blockDim.x + threadIdx.x;
    if (i >= n) return;
    int rs = g_rowtmp[i] + g_spine[i >> 8];
    g_row[i] = rs;
    g_cur[i] = rs;
    g_dinv[i] = rsqrtf((float)(g_deg[i] + 1));      // +1 self-loop
    if (i == 0) g_row[n] = E;
}

// per-block dtype detect + CSR fill from raw edges
__global__ void k_fill(const int* __restrict__ e32, int E) {
    __shared__ int s_is64;
    if (threadIdx.x == 0) s_is64 = 1;
    __syncthreads();
    if (e32[2 * threadIdx.x + 1] != 0) s_is64 = 0;
    __syncthreads();
    int is64 = s_is64;
    int i = blockIdx.x * blockDim.x + threadIdx.x;
    if (i >= E) return;
    int s, d;
    if (is64) {
        const long long* p = (const long long*)e32;
        s = (int)p[i]; d = (int)p[E + i];
    } else {
        s = e32[i]; d = e32[E + i];
    }
    int pos = atomicAdd(&g_cur[d], 1);
    g_csrc[pos] = s;
    g_csw[pos] = g_dinv[s];
}

// W split: g_wh/g_wl[l][n][k] = bf16 hi/lo of W[l][k][n] (transposed, all 3 layers)
__global__ void k_wsplit(const float* __restrict__ W) {
    int i = blockIdx.x * blockDim.x + threadIdx.x;
    if (i >= 3 * D * D) return;
    int l = i >> 14, r = (i >> 7) & 127, c = i & 127;   // out [l][n=r][k=c]
    float v = W[l * D * D + c * D + r];
    __nv_bfloat16 h = __float2bfloat16(v);
    g_wh[i] = h;
    g_wl[i] = __float2bfloat16(v - __bfloat162float(h));
}

// ============================================================================
// Tensor-core GEMM via mma.sync (bf16 hi/lo compensated, fp32 accum):
//   g_y[tile 128 rows][128] = x @ W[layer]
// smem (word view), row stride 68 words (136 bf16 = 272B, conflict-free):
//   AH @0, AL @8704, BH @17408, BL @26112   (139,264 bytes total)
// 8 warps in 4(M)x2(N) grid; each warp: 32x64 -> 2 m-tiles x 8 n-tiles.
// NOTE: weights are read from the device symbols g_wh/g_wl via a layer index
// (passing host-side g_wh+offset is UB: host shadow address + GB300 ATS reads
// host zeros silently — the R9 bug).
// ============================================================================
__global__ __launch_bounds__(256, 1)
void k_gemm_mma(const float* __restrict__ x, int layer, int n) {
    extern __shared__ uint32_t S[];
    const int AH = 0, AL = 8704, BH = 17408, BL = 26112;   // word offsets
    const int tid = threadIdx.x;
    const int row0 = blockIdx.x * 128;

    const uint32_t* wh = (const uint32_t*)(g_wh + (size_t)layer * D * D);
    const uint32_t* wl = (const uint32_t*)(g_wl + (size_t)layer * D * D);

    // ---- stage W^T hi/lo: 128 n-rows x 64 words = 8192 b32 words ----
#pragma unroll
    for (int it = 0; it < 32; it++) {
        int i = tid + it * 256;                 // 0..8191
        int nr = i >> 6, kc = i & 63;
        uint32_t off = nr * 68 + kc;
        S[BH + off] = wh[i];
        S[BL + off] = wl[i];
    }

    // ---- stage x tile: fp32 -> bf16 hi + lo (128 rows x 32 float4) ----
#pragma unroll
    for (int it = 0; it < 16; it++) {
        int i = tid + it * 256;                 // 0..4095
        int r = i >> 5, c4 = i & 31;
        int gr = row0 + r;
        float4 f = make_float4(0.f, 0.f, 0.f, 0.f);
        if (gr < n) f = ((const float4*)(x + (size_t)gr * D))[c4];
        float hx = __bfloat162float(__float2bfloat16(f.x));
        float hy = __bfloat162float(__float2bfloat16(f.y));
        float hz = __bfloat162float(__float2bfloat16(f.z));
        float hw = __bfloat162float(__float2bfloat16(f.w));
        uint32_t h0, h1, l0, l1;
        CVT_BF16X2(h0, f.x, f.y);
        CVT_BF16X2(h1, f.z, f.w);
        CVT_BF16X2(l0, f.x - hx, f.y - hy);
        CVT_BF16X2(l1, f.z - hz, f.w - hw);
        uint32_t off = r * 68 + c4 * 2;
        *(uint2*)(S + AH + off) = make_uint2(h0, h1);
        *(uint2*)(S + AL + off) = make_uint2(l0, l1);
    }
    __syncthreads();

    // ---- mainloop ----
    const int lane = tid & 31, wid = tid >> 5;
    const int wr = wid & 3, wc = wid >> 2;      // warp M-slot (32), N-slot (64)
    const int g = lane >> 2, tg = lane & 3;
    const int arow = wr * 32;
    const int nb0 = wc * 64;

    float acc[2][8][4];
#pragma unroll
    for (int mt = 0; mt < 2; mt++)
#pragma unroll
        for (int nt = 0; nt < 8; nt++)
#pragma unroll
            for (int q = 0; q < 4; q++) acc[mt][nt][q] = 0.f;

#pragma unroll
    for (int ks = 0; ks < 8; ks++) {
        const int kw = ks * 8 + tg;             // word offset in row for this lane
        uint32_t ah[2][4], al[2][4];
#pragma unroll
        for (int mt = 0; mt < 2; mt++) {
            uint32_t base = (uint32_t)(arow + mt * 16 + g) * 68 + kw;
            ah[mt][0] = S[AH + base];
            ah[mt][1] = S[AH + base + 8 * 68];
            ah[mt][2] = S[AH + base + 4];
            ah[mt][3] = S[AH + base + 8 * 68 + 4];
            al[mt][0] = S[AL + base];
            al[mt][1] = S[AL + base + 8 * 68];
            al[mt][2] = S[AL + base + 4];
            al[mt][3] = S[AL + base + 8 * 68 + 4];
        }
#pragma unroll
        for (int nt = 0; nt < 8; nt++) {
            uint32_t bbase = (uint32_t)(nb0 + nt * 8 + g) * 68 + kw;
            uint32_t bh0 = S[BH + bbase], bh1 = S[BH + bbase + 4];
            uint32_t bl0 = S[BL + bbase], bl1 = S[BL + bbase + 4];
#pragma unroll
            for (int mt = 0; mt < 2; mt++) {
                MMA_BF16(acc[mt][nt], ah[mt], bh0, bh1);   // xh*Wh
                MMA_BF16(acc[mt][nt], ah[mt], bl0, bl1);   // xh*Wl
                MMA_BF16(acc[mt][nt], al[mt], bh0, bh1);   // xl*Wh
            }
        }
    }

    // ---- writeback (32B-sector-aligned float2 stores) ----
#pragma unroll
    for (int mt = 0; mt < 2; mt++) {
        int r0g = row0 + arow + mt * 16 + g;
        int r1g = r0g + 8;
#pragma unroll
        for (int nt = 0; nt < 8; nt++) {
            int c = nb0 + nt * 8 + tg * 2;
            if (r0g < n)
                *(float2*)(g_y + (size_t)r0g * D + c) = make_float2(acc[mt][nt][0], acc[mt][nt][1]);
            if (r1g < n)
                *(float2*)(g_y + (size_t)r1g * D + c) = make_float2(acc[mt][nt][2], acc[mt][nt][3]);
        }
    }
}

// ============================================================================
// CSR gather: xout[i] = b + dinv[i]^2*y[i] + dinv[i]*sum_e( dinv[src]*y[src] )
// final layer also writes total = x0+x1+x2+x3
// ============================================================================
__global__ __launch_bounds__(256) void k_gather(const float* __restrict__ bias,
                                                float* __restrict__ xout,
                                                const float* __restrict__ x0,
                                                const float* __restrict__ x1,
                                                const float* __restrict__ x2,
                                                float* __restrict__ total,
                                                int n, int final_layer) {
    int w = (blockIdx.x * blockDim.x + threadIdx.x) >> 5;
    if (w >= n) return;
    int lane = threadIdx.x & 31;
    const float4* yb = (const float4*)g_y;
    const size_t idx = (size_t)w * 32 + lane;

    float di = g_dinv[w];
    float4 ys = yb[idx];
    float4 acc;
    acc.x = ys.x * di; acc.y = ys.y * di; acc.z = ys.z * di; acc.w = ys.w * di;

    int e = g_row[w];
    const int e1 = g_row[w + 1];
    for (; e + 1 < e1; e += 2) {
        int   s0 = g_csrc[e],   s1 = g_csrc[e + 1];
        float u0 = g_csw[e],    u1 = g_csw[e + 1];
        float4 v0 = yb[(size_t)s0 * 32 + lane];
        float4 v1 = yb[(size_t)s1 * 32 + lane];
        acc.x = fmaf(u0, v0.x, acc.x); acc.y = fmaf(u0, v0.y, acc.y);
        acc.z = fmaf(u0, v0.z, acc.z); acc.w = fmaf(u0, v0.w, acc.w);
        acc.x = fmaf(u1, v1.x, acc.x); acc.y = fmaf(u1, v1.y, acc.y);
        acc.z = fmaf(u1, v1.z, acc.z); acc.w = fmaf(u1, v1.w, acc.w);
    }
    if (e < e1) {
        int s0 = g_csrc[e];
        float u0 = g_csw[e];
        float4 v0 = yb[(size_t)s0 * 32 + lane];
        acc.x = fmaf(u0, v0.x, acc.x); acc.y = fmaf(u0, v0.y, acc.y);
        acc.z = fmaf(u0, v0.z, acc.z); acc.w = fmaf(u0, v0.w, acc.w);
    }

    float4 bv = ((const float4*)bias)[lane];
    float4 res;
    res.x = fmaf(acc.x, di, bv.x);
    res.y = fmaf(acc.y, di, bv.y);
    res.z = fmaf(acc.z, di, bv.z);
    res.w = fmaf(acc.w, di, bv.w);
    ((float4*)xout)[idx] = res;

    if (final_layer) {
        float4 a = ((const float4*)x0)[idx];
        float4 b2 = ((const float4*)x1)[idx];
        float4 c = ((const float4*)x2)[idx];
        float4 t;
        t.x = a.x + b2.x + c.x + res.x;
        t.y = a.y + b2.y + c.y + res.y;
        t.z = a.z + b2.z + c.z + res.z;
        t.w = a.w + b2.w + c.w + res.w;
        ((float4*)total)[idx] = t;
    }
}

extern "C" void kernel_launch(void* const* d_in, const int* in_sizes, int n_in,
                              void* d_out, int out_size) {
    const float* item_emb = (const float*)d_in[0];
    const float* weights  = (const float*)d_in[1];
    const float* biases   = (const float*)d_in[2];
    const int*   edges    = (const int*)d_in[3];

    const int emb_rows = in_sizes[0] / D;
    const int E        = in_sizes[3] / 2;
    const int n        = out_size / (5 * D);
    float* out = (float*)d_out;
    const size_t nd = (size_t)n * D;
    const int nd4 = (int)(nd / 4);

    const float* x0src = item_emb + (size_t)(emb_rows - n) * D;

    static int attr_done = 0;
    const int GEMM_SMEM = 139264;
    if (!attr_done) {
        cudaFuncSetAttribute(k_gemm_mma, cudaFuncAttributeMaxDynamicSharedMemorySize, GEMM_SMEM);
        attr_done = 1;
    }

    // setup
    k_copy_init<<<(nd4 + 255) / 256, 256>>>((const float4*)x0src, (float4*)(out + nd), nd4, n);
    k_count<<<(E + 255) / 256, 256>>>(edges, E);
    const int nb = (n + 255) / 256;
    k_scan1<<<nb, 256>>>(n);
    k_scan2<<<1, 1024>>>(nb);
    k_scan3<<<nb, 256>>>(n, E);
    k_fill<<<(E + 255) / 256, 256>>>(edges, E);
    k_wsplit<<<(3 * D * D + 255) / 256, 256>>>(weights);

    const int gblocks = (n + 127) / 128;
    const int sblocks = (n + 7) / 8;
    for (int l = 0; l < 3; l++) {
        const float* xin = out + nd * (size_t)(1 + l);
        float* xout      = out + nd * (size_t)(2 + l);
        k_gemm_mma<<<gblocks, 256, GEMM_SMEM>>>(xin, l, n);
        k_gather<<<sblocks, 256>>>(biases + (size_t)l * D, xout,
                                   out + nd, out + 2 * nd, out + 3 * nd, out,
                                   n, (l == 2) ? 1 : 0);
    }
}

// round 11
// speedup vs baseline: 2.1505x; 1.0752x over previous
#include <cuda_runtime.h>
#include <cuda_bf16.h>
#include <cstdint>

#define D 128
#define MAXN 50176
#define MAXE (1 << 20)

// ---- scratch (static device globals; no allocation) ----
__device__ float g_y[(size_t)MAXN * D];     // per-layer x@W (fp32)
__device__ float g_dinv[MAXN];
__device__ int   g_deg[MAXN];               // MUST be zero at entry (zeroed at end of k_fill)
__device__ int   g_row[MAXN + 1];           // CSR row_start (by dst)
__device__ int   g_rowtmp[MAXN];
__device__ int   g_cur[MAXN];
__device__ int   g_spine[1024];
__device__ uint2 g_cpack[MAXE];             // CSR slot: {src, bits(dinv[src])}
__device__ __nv_bfloat16 g_wh[3 * D * D];   // W^T hi (B layout: [n][k])
__device__ __nv_bfloat16 g_wl[3 * D * D];   // W^T lo

// pack two f32 -> bf16x2 word: lower half = lo_f, upper half = hi_f
#define CVT_BF16X2(res, lo_f, hi_f) \
    asm("cvt.rn.satfinite.bf16x2.f32 %0, %1, %2;" : "=r"(res) : "f"(hi_f), "f"(lo_f))

// D += A * B  (m16n8k16, bf16 in, f32 accum)
#define MMA_BF16(c, a, b0, b1)                                                  \
    asm volatile("mma.sync.aligned.m16n8k16.row.col.f32.bf16.bf16.f32 "         \
        "{%0,%1,%2,%3}, {%4,%5,%6,%7}, {%8,%9}, {%0,%1,%2,%3};"                 \
        : "+f"((c)[0]), "+f"((c)[1]), "+f"((c)[2]), "+f"((c)[3])                \
        : "r"((a)[0]), "r"((a)[1]), "r"((a)[2]), "r"((a)[3]), "r"(b0), "r"(b1))

// ============================================================================
// k_prep: fused x0-copy + W hi/lo split + degree count (independent work,
// dispatched by blockIdx range). Requires g_deg == 0 on entry.
// ============================================================================
__global__ void k_prep(const float4* __restrict__ x0src, float4* __restrict__ x0dst,
                       int n4, const float* __restrict__ W,
                       const int* __restrict__ e32, int E,
                       int nbCopy, int nbW) {
    int b = blockIdx.x;
    if (b < nbCopy) {
        int i = b * 256 + threadIdx.x;
        if (i < n4) x0dst[i] = x0src[i];
    } else if (b < nbCopy + nbW) {
        int i = (b - nbCopy) * 256 + threadIdx.x;
        if (i < 3 * D * D) {
            int l = i >> 14, r = (i >> 7) & 127, c = i & 127;   // out [l][n=r][k=c]
            float v = W[l * D * D + c * D + r];
            __nv_bfloat16 h = __float2bfloat16(v);
            g_wh[i] = h;
            g_wl[i] = __float2bfloat16(v - __bfloat162float(h));
        }
    } else {
        // degree count (with per-block int64/int32 dtype detection)
        __shared__ int s_is64;
        if (threadIdx.x == 0) s_is64 = 1;
        __syncthreads();
        if (e32[2 * threadIdx.x + 1] != 0) s_is64 = 0;   // benign race
        __syncthreads();
        int is64 = s_is64;
        int i = (b - nbCopy - nbW) * 256 + threadIdx.x;
        if (i < E) {
            int d = is64 ? (int)((const long long*)e32)[E + i] : e32[E + i];
            atomicAdd(&g_deg[d], 1);
        }
    }
}

// ---- scan pass 1: per-block exclusive scan + block totals ----
__global__ __launch_bounds__(256) void k_scan1(int n) {
    __shared__ int sh[256];
    int i = blockIdx.x * 256 + threadIdx.x;
    int v = (i < n) ? g_deg[i] : 0;
    sh[threadIdx.x] = v;
    __syncthreads();
#pragma unroll
    for (int off = 1; off < 256; off <<= 1) {
        int t = (threadIdx.x >= off) ? sh[threadIdx.x - off] : 0;
        __syncthreads();
        sh[threadIdx.x] += t;
        __syncthreads();
    }
    if (i < n) g_rowtmp[i] = sh[threadIdx.x] - v;
    if (threadIdx.x == 255) g_spine[blockIdx.x] = sh[255];
}

// ---- scan pass 2: each block sums spine[0..blockIdx) itself, finalizes row/cur/dinv ----
__global__ __launch_bounds__(256) void k_scan23(int n, int E, int nb) {
    __shared__ int sh[256];
    int t = threadIdx.x;
    sh[t] = (t < blockIdx.x && t < nb) ? g_spine[t] : 0;
    __syncthreads();
#pragma unroll
    for (int off = 128; off > 0; off >>= 1) {
        if (t < off) sh[t] += sh[t + off];
        __syncthreads();
    }
    int base = sh[0];
    int i = blockIdx.x * 256 + t;
    if (i < n) {
        int rs = g_rowtmp[i] + base;
        g_row[i] = rs;
        g_cur[i] = rs;
        g_dinv[i] = rsqrtf((float)(g_deg[i] + 1));   // +1 self-loop
        if (i == 0) g_row[n] = E;
    }
}

// ---- CSR fill (packed src+weight), then zero g_deg for the next graph replay ----
__global__ void k_fill(const int* __restrict__ e32, int E, int n) {
    __shared__ int s_is64;
    if (threadIdx.x == 0) s_is64 = 1;
    __syncthreads();
    if (e32[2 * threadIdx.x + 1] != 0) s_is64 = 0;
    __syncthreads();
    int is64 = s_is64;
    int i = blockIdx.x * blockDim.x + threadIdx.x;
    if (i < E) {
        int s, d;
        if (is64) {
            const long long* p = (const long long*)e32;
            s = (int)p[i]; d = (int)p[E + i];
        } else {
            s = e32[i]; d = e32[E + i];
        }
        int pos = atomicAdd(&g_cur[d], 1);
        g_cpack[pos] = make_uint2((unsigned)s, __float_as_uint(g_dinv[s]));
    }
    if (i < n) g_deg[i] = 0;     // reset for next replay (deg is dead from here on)
}

// ============================================================================
// Tensor-core GEMM via mma.sync (bf16 hi/lo compensated, fp32 accum):
//   g_y[tile 128 rows][128] = x @ W[layer]
// smem word view, row stride 68 (136 bf16 = 272B): AH@0 AL@8704 BH@17408 BL@26112
// 8 warps in 4(M)x2(N); weights read via device symbols (host-shadow UB avoided).
// ============================================================================
__global__ __launch_bounds__(256, 1)
void k_gemm_mma(const float* __restrict__ x, int layer, int n) {
    extern __shared__ uint32_t S[];
    const int AH = 0, AL = 8704, BH = 17408, BL = 26112;
    const int tid = threadIdx.x;
    const int row0 = blockIdx.x * 128;

    const uint32_t* wh = (const uint32_t*)(g_wh + (size_t)layer * D * D);
    const uint32_t* wl = (const uint32_t*)(g_wl + (size_t)layer * D * D);

    // ---- stage W^T hi/lo: 128 n-rows x 64 words = 8192 words ----
#pragma unroll
    for (int it = 0; it < 32; it++) {
        int i = tid + it * 256;
        int nr = i >> 6, kc = i & 63;
        uint32_t off = nr * 68 + kc;
        S[BH + off] = wh[i];
        S[BL + off] = wl[i];
    }

    // ---- stage x tile: fp32 -> bf16 hi + lo (128 rows x 32 float4) ----
#pragma unroll
    for (int it = 0; it < 16; it++) {
        int i = tid + it * 256;
        int r = i >> 5, c4 = i & 31;
        int gr = row0 + r;
        float4 f = make_float4(0.f, 0.f, 0.f, 0.f);
        if (gr < n) f = ((const float4*)(x + (size_t)gr * D))[c4];
        float hx = __bfloat162float(__float2bfloat16(f.x));
        float hy = __bfloat162float(__float2bfloat16(f.y));
        float hz = __bfloat162float(__float2bfloat16(f.z));
        float hw = __bfloat162float(__float2bfloat16(f.w));
        uint32_t h0, h1, l0, l1;
        CVT_BF16X2(h0, f.x, f.y);
        CVT_BF16X2(h1, f.z, f.w);
        CVT_BF16X2(l0, f.x - hx, f.y - hy);
        CVT_BF16X2(l1, f.z - hz, f.w - hw);
        uint32_t off = r * 68 + c4 * 2;
        *(uint2*)(S + AH + off) = make_uint2(h0, h1);
        *(uint2*)(S + AL + off) = make_uint2(l0, l1);
    }
    __syncthreads();

    // ---- mainloop ----
    const int lane = tid & 31, wid = tid >> 5;
    const int wr = wid & 3, wc = wid >> 2;
    const int g = lane >> 2, tg = lane & 3;
    const int arow = wr * 32;
    const int nb0 = wc * 64;

    float acc[2][8][4];
#pragma unroll
    for (int mt = 0; mt < 2; mt++)
#pragma unroll
        for (int nt = 0; nt < 8; nt++)
#pragma unroll
            for (int q = 0; q < 4; q++) acc[mt][nt][q] = 0.f;

#pragma unroll
    for (int ks = 0; ks < 8; ks++) {
        const int kw = ks * 8 + tg;
        uint32_t ah[2][4], al[2][4];
#pragma unroll
        for (int mt = 0; mt < 2; mt++) {
            uint32_t base = (uint32_t)(arow + mt * 16 + g) * 68 + kw;
            ah[mt][0] = S[AH + base];
            ah[mt][1] = S[AH + base + 8 * 68];
            ah[mt][2] = S[AH + base + 4];
            ah[mt][3] = S[AH + base + 8 * 68 + 4];
            al[mt][0] = S[AL + base];
            al[mt][1] = S[AL + base + 8 * 68];
            al[mt][2] = S[AL + base + 4];
            al[mt][3] = S[AL + base + 8 * 68 + 4];
        }
#pragma unroll
        for (int nt = 0; nt < 8; nt++) {
            uint32_t bbase = (uint32_t)(nb0 + nt * 8 + g) * 68 + kw;
            uint32_t bh0 = S[BH + bbase], bh1 = S[BH + bbase + 4];
            uint32_t bl0 = S[BL + bbase], bl1 = S[BL + bbase + 4];
#pragma unroll
            for (int mt = 0; mt < 2; mt++) {
                MMA_BF16(acc[mt][nt], ah[mt], bh0, bh1);   // xh*Wh
                MMA_BF16(acc[mt][nt], ah[mt], bl0, bl1);   // xh*Wl
                MMA_BF16(acc[mt][nt], al[mt], bh0, bh1);   // xl*Wh
            }
        }
    }

    // ---- writeback (32B-sector-aligned float2 stores) ----
#pragma unroll
    for (int mt = 0; mt < 2; mt++) {
        int r0g = row0 + arow + mt * 16 + g;
        int r1g = r0g + 8;
#pragma unroll
        for (int nt = 0; nt < 8; nt++) {
            int c = nb0 + nt * 8 + tg * 2;
            if (r0g < n)
                *(float2*)(g_y + (size_t)r0g * D + c) = make_float2(acc[mt][nt][0], acc[mt][nt][1]);
            if (r1g < n)
                *(float2*)(g_y + (size_t)r1g * D + c) = make_float2(acc[mt][nt][2], acc[mt][nt][3]);
        }
    }
}

// ============================================================================
// CSR gather: xout[i] = b + dinv[i]^2*y[i] + dinv[i]*sum_e( w_e*y[src_e] )
// final layer also writes total = x0+x1+x2+x3
// ============================================================================
__device__ __forceinline__ void fma_row(float4& acc, float u, const float4& v) {
    acc.x = fmaf(u, v.x, acc.x); acc.y = fmaf(u, v.y, acc.y);
    acc.z = fmaf(u, v.z, acc.z); acc.w = fmaf(u, v.w, acc.w);
}

__global__ __launch_bounds__(256) void k_gather(const float* __restrict__ bias,
                                                float* __restrict__ xout,
                                                const float* __restrict__ x0,
                                                const float* __restrict__ x1,
                                                const float* __restrict__ x2,
                                                float* __restrict__ total,
                                                int n, int final_layer) {
    int w = (blockIdx.x * blockDim.x + threadIdx.x) >> 5;
    if (w >= n) return;
    int lane = threadIdx.x & 31;
    const float4* yb = (const float4*)g_y;
    const size_t idx = (size_t)w * 32 + lane;

    float di = g_dinv[w];
    float4 ys = yb[idx];
    float4 acc;
    acc.x = ys.x * di; acc.y = ys.y * di; acc.z = ys.z * di; acc.w = ys.w * di;

    int e = g_row[w];
    const int e1 = g_row[w + 1];
    for (; e + 3 < e1; e += 4) {
        uint2 p0 = g_cpack[e],     p1 = g_cpack[e + 1];
        uint2 p2 = g_cpack[e + 2], p3 = g_cpack[e + 3];
        float4 v0 = yb[(size_t)p0.x * 32 + lane];
        float4 v1 = yb[(size_t)p1.x * 32 + lane];
        float4 v2 = yb[(size_t)p2.x * 32 + lane];
        float4 v3 = yb[(size_t)p3.x * 32 + lane];
        fma_row(acc, __uint_as_float(p0.y), v0);
        fma_row(acc, __uint_as_float(p1.y), v1);
        fma_row(acc, __uint_as_float(p2.y), v2);
        fma_row(acc, __uint_as_float(p3.y), v3);
    }
    for (; e < e1; e++) {
        uint2 p0 = g_cpack[e];
        float4 v0 = yb[(size_t)p0.x * 32 + lane];
        fma_row(acc, __uint_as_float(p0.y), v0);
    }

    float4 bv = ((const float4*)bias)[lane];
    float4 res;
    res.x = fmaf(acc.x, di, bv.x);
    res.y = fmaf(acc.y, di, bv.y);
    res.z = fmaf(acc.z, di, bv.z);
    res.w = fmaf(acc.w, di, bv.w);
    ((float4*)xout)[idx] = res;

    if (final_layer) {
        float4 a = ((const float4*)x0)[idx];
        float4 b2 = ((const float4*)x1)[idx];
        float4 c = ((const float4*)x2)[idx];
        float4 t;
        t.x = a.x + b2.x + c.x + res.x;
        t.y = a.y + b2.y + c.y + res.y;
        t.z = a.z + b2.z + c.z + res.z;
        t.w = a.w + b2.w + c.w + res.w;
        ((float4*)total)[idx] = t;
    }
}

extern "C" void kernel_launch(void* const* d_in, const int* in_sizes, int n_in,
                              void* d_out, int out_size) {
    const float* item_emb = (const float*)d_in[0];
    const float* weights  = (const float*)d_in[1];
    const float* biases   = (const float*)d_in[2];
    const int*   edges    = (const int*)d_in[3];

    const int emb_rows = in_sizes[0] / D;
    const int E        = in_sizes[3] / 2;
    const int n        = out_size / (5 * D);
    float* out = (float*)d_out;
    const size_t nd = (size_t)n * D;
    const int nd4 = (int)(nd / 4);

    const float* x0src = item_emb + (size_t)(emb_rows - n) * D;

    static int attr_done = 0;
    const int GEMM_SMEM = 139264;
    if (!attr_done) {
        cudaFuncSetAttribute(k_gemm_mma, cudaFuncAttributeMaxDynamicSharedMemorySize, GEMM_SMEM);
        attr_done = 1;
    }

    // fused setup: copy x0 + W split + degree count (g_deg zeroed by prior k_fill)
    const int nbCopy = (nd4 + 255) / 256;
    const int nbW    = (3 * D * D + 255) / 256;
    const int nbE    = (E + 255) / 256;
    k_prep<<<nbCopy + nbW + nbE, 256>>>((const float4*)x0src, (float4*)(out + nd),
                                        nd4, weights, edges, E, nbCopy, nbW);
    const int nb = (n + 255) / 256;
    k_scan1<<<nb, 256>>>(n);
    k_scan23<<<nb, 256>>>(n, E, nb);
    k_fill<<<nbE, 256>>>(edges, E, n);

    const int gblocks = (n + 127) / 128;
    const int sblocks = (n + 7) / 8;
    for (int l = 0; l < 3; l++) {
        const float* xin = out + nd * (size_t)(1 + l);
        float* xout      = out + nd * (size_t)(2 + l);
        k_gemm_mma<<<gblocks, 256, GEMM_SMEM>>>(xin, l, n);
        k_gather<<<sblocks, 256>>>(biases + (size_t)l * D, xout,
                                   out + nd, out + 2 * nd, out + 3 * nd, out,
                                   n, (l == 2) ? 1 : 0);
    }
}